// round 2
// baseline (speedup 1.0000x reference)
#include <cuda_runtime.h>
#include <math.h>

#define NN 2048
#define DD 128

__constant__ int c_xidx[4] = {4, 9, 14, 19};
__constant__ int c_eidx[4] = {0, 4, 9, 14};

// ---------------- static device scratch ----------------
__device__ unsigned d_bitmask[4][NN][64];     // mask bitmaps per step
__device__ float    d_Wh[4][NN][DD];          // per-gate projected features
__device__ float4   d_rowinfo[4][NN];         // {-s_src, exp(s_src), exp(a*s_src), 0}
__device__ float4   d_colinfo[4][NN];         // { s_dst, exp(s_dst), exp(a*s_dst), 0}
__device__ float    d_gates[4][NN * DD];      // elu(attn@Wh) per gate
__device__ float    d_cell[NN * DD];
__device__ float    d_hidden[NN * DD];
__device__ float    d_outs[4][NN * DD];       // sigmoid(hidden@W+b) per step [t][n][c]
__device__ float    d_y1[3][NN * DD];
__device__ float    d_y2[2][NN * DD];
__device__ float    d_convwT[3][256][DD];     // conv weights: [l][s*128+c][o]

// ---------------- init: cell = actors[:,0,:], hidden = h0 ----------------
__global__ void k_init(const float* __restrict__ actors, const float* __restrict__ h0) {
    int idx = blockIdx.x * blockDim.x + threadIdx.x;
    if (idx >= NN * DD) return;
    int n = idx >> 7, dd = idx & 127;
    d_cell[idx]   = actors[(size_t)n * 20 * DD + dd];
    d_hidden[idx] = h0[dd];
}

// ---------------- pack adjacency slices into bitmasks (all 4 steps) ----------------
__global__ void k_pack(const int* __restrict__ G) {
    int wid  = (blockIdx.x * blockDim.x + threadIdx.x) >> 5;
    int lane = threadIdx.x & 31;
    int word = wid & 63;
    int n    = (wid >> 6) & (NN - 1);
    int t    = wid >> 17;
    int e    = c_eidx[t];
    int m    = (word << 5) + lane;
    int v    = G[(size_t)n * 20 * NN + (size_t)e * NN + m];
    unsigned b = __ballot_sync(0xffffffffu, v > 0);
    if (lane == 0) d_bitmask[t][n][word] = b;
}

// ---------------- transpose conv weights ----------------
__global__ void k_transposeW(const float* __restrict__ convw) {
    int idx = blockIdx.x * blockDim.x + threadIdx.x;
    if (idx >= 3 * 256 * DD) return;
    int o = idx & 127;
    int k = (idx >> 7) & 255;
    int l = idx >> 15;
    int c = k & 127, s = k >> 7;
    d_convwT[l][k][o] = convw[(((size_t)l * 128 + o) * 128 + c) * 2 + s];
}

// ---------------- Wh = [X_t | hidden] @ Wg ----------------
__global__ __launch_bounds__(256) void k_wh(const float* __restrict__ actors,
                                            const float* __restrict__ Wg, int t) {
    __shared__ __align__(16) float As[16][68];
    __shared__ __align__(16) float Bs[16][68];
    int tid = threadIdx.x;
    int n0  = blockIdx.x * 64;
    int g   = blockIdx.y >> 1;
    int d0  = (blockIdx.y & 1) * 64;
    int tx  = tid & 15, ty = tid >> 4;
    float acc[4][4] = {};
    int xoff = c_xidx[t] * DD;
    int la_n = tid >> 2;
    int la_k = (tid & 3) * 4;
    int lb_k = tid >> 4;
    int lb_d = (tid & 15) * 4;
    for (int k0 = 0; k0 < 256; k0 += 16) {
        __syncthreads();
        int f = k0 + la_k;
        float4 av;
        if (f < 128) av = *(const float4*)&actors[(size_t)(n0 + la_n) * 2560 + xoff + f];
        else         av = *(const float4*)&d_hidden[(n0 + la_n) * DD + f - 128];
        As[la_k + 0][la_n] = av.x; As[la_k + 1][la_n] = av.y;
        As[la_k + 2][la_n] = av.z; As[la_k + 3][la_n] = av.w;
        *(float4*)&Bs[lb_k][lb_d] =
            *(const float4*)&Wg[((size_t)g * 256 + k0 + lb_k) * DD + d0 + lb_d];
        __syncthreads();
#pragma unroll
        for (int kk = 0; kk < 16; kk++) {
            float4 a = *(float4*)&As[kk][ty * 4];
            float4 b = *(float4*)&Bs[kk][tx * 4];
            float ar[4] = {a.x, a.y, a.z, a.w};
            float br[4] = {b.x, b.y, b.z, b.w};
#pragma unroll
            for (int i = 0; i < 4; i++)
#pragma unroll
                for (int j = 0; j < 4; j++) acc[i][j] = fmaf(ar[i], br[j], acc[i][j]);
        }
    }
#pragma unroll
    for (int i = 0; i < 4; i++) {
        int row = n0 + ty * 4 + i;
        float4 o = make_float4(acc[i][0], acc[i][1], acc[i][2], acc[i][3]);
        *(float4*)&d_Wh[g][row][d0 + tx * 4] = o;
    }
}

// ---------------- per-(g,n) scores + factorized exps ----------------
__global__ void k_prep(const float* __restrict__ ag) {
    int gid  = (blockIdx.x * blockDim.x + threadIdx.x) >> 5;
    int lane = threadIdx.x & 31;
    int g = gid >> 11, n = gid & 2047;
    float4 wv = *(const float4*)&d_Wh[g][n][lane * 4];
    float4 as = *(const float4*)&ag[g * 256 + lane * 4];
    float4 ad = *(const float4*)&ag[g * 256 + 128 + lane * 4];
    float s1 = wv.x * as.x + wv.y * as.y + wv.z * as.z + wv.w * as.w;
    float s2 = wv.x * ad.x + wv.y * ad.y + wv.z * ad.z + wv.w * ad.w;
#pragma unroll
    for (int off = 16; off; off >>= 1) {
        s1 += __shfl_xor_sync(0xffffffffu, s1, off);
        s2 += __shfl_xor_sync(0xffffffffu, s2, off);
    }
    if (lane == 0) {
        d_rowinfo[g][n] = make_float4(-s1, expf(s1), expf(0.2f * s1), 0.f);
        d_colinfo[g][n] = make_float4(s2, expf(s2), expf(0.2f * s2), 0.f);
    }
}

__device__ __forceinline__ float eluf(float x) { return x > 0.f ? x : expm1f(x); }

// ---------------- attention + elu ----------------
// Block: 8 warps; each warp owns 4 rows (full 128 dims, 4 per lane). m chunked by 64.
__global__ __launch_bounds__(256) void k_attn(int t) {
    __shared__ __align__(16) float  sWh[64 * DD];   // 32 KB
    __shared__ float4 sCol[64];
    __shared__ float4 sCoef[8 * 64];
    const int g    = blockIdx.y;
    const int warp = threadIdx.x >> 5;
    const int lane = threadIdx.x & 31;
    const int tid  = threadIdx.x;
    const int n0   = blockIdx.x * 32 + warp * 4;

    float thr[4], A1[4], A2[4];
#pragma unroll
    for (int r = 0; r < 4; r++) {
        float4 ri = d_rowinfo[g][n0 + r];
        thr[r] = ri.x; A1[r] = ri.y; A2[r] = ri.z;
    }
    const unsigned* bm0 = &d_bitmask[t][n0][0];   // 4 rows, stride 64 words
    const float* Whg = &d_Wh[g][0][0];

    float4 acc[4] = {make_float4(0,0,0,0), make_float4(0,0,0,0),
                     make_float4(0,0,0,0), make_float4(0,0,0,0)};
    float den[4] = {0.f, 0.f, 0.f, 0.f};

    for (int m0 = 0; m0 < NN; m0 += 64) {
        __syncthreads();
        {
            const float4* src = (const float4*)(Whg + m0 * DD);
            float4* dst = (float4*)sWh;
#pragma unroll
            for (int i = 0; i < 8; i++) dst[tid + 256 * i] = src[tid + 256 * i];
            if (tid < 64) sCol[tid] = d_colinfo[g][m0 + tid];
        }
        __syncthreads();

        unsigned bw0[4], bw1[4];
        int wbase = m0 >> 5;
#pragma unroll
        for (int r = 0; r < 4; r++) {
            bw0[r] = bm0[r * 64 + wbase];
            bw1[r] = bm0[r * 64 + wbase + 1];
        }
#pragma unroll
        for (int k = 0; k < 2; k++) {
            float4 ci = sCol[lane + 32 * k];
            float co[4];
#pragma unroll
            for (int r = 0; r < 4; r++) {
                unsigned w = k ? bw1[r] : bw0[r];
                bool act = (w >> lane) & 1u;
                float cf = (ci.x >= thr[r]) ? A1[r] * ci.y : A2[r] * ci.z;
                cf = act ? cf : 0.f;
                den[r] += cf;
                co[r] = cf;
            }
            sCoef[warp * 64 + lane + 32 * k] = make_float4(co[0], co[1], co[2], co[3]);
        }
        __syncwarp();

        const float4* wrow = (const float4*)sWh;
        const float4* cf4  = &sCoef[warp * 64];
#pragma unroll 8
        for (int j = 0; j < 64; j++) {
            float4 co = cf4[j];
            float4 v  = wrow[j * 32 + lane];
            acc[0].x = fmaf(co.x, v.x, acc[0].x); acc[0].y = fmaf(co.x, v.y, acc[0].y);
            acc[0].z = fmaf(co.x, v.z, acc[0].z); acc[0].w = fmaf(co.x, v.w, acc[0].w);
            acc[1].x = fmaf(co.y, v.x, acc[1].x); acc[1].y = fmaf(co.y, v.y, acc[1].y);
            acc[1].z = fmaf(co.y, v.z, acc[1].z); acc[1].w = fmaf(co.y, v.w, acc[1].w);
            acc[2].x = fmaf(co.z, v.x, acc[2].x); acc[2].y = fmaf(co.z, v.y, acc[2].y);
            acc[2].z = fmaf(co.z, v.z, acc[2].z); acc[2].w = fmaf(co.z, v.w, acc[2].w);
            acc[3].x = fmaf(co.w, v.x, acc[3].x); acc[3].y = fmaf(co.w, v.y, acc[3].y);
            acc[3].z = fmaf(co.w, v.z, acc[3].z); acc[3].w = fmaf(co.w, v.w, acc[3].w);
        }
    }

#pragma unroll
    for (int r = 0; r < 4; r++) {
#pragma unroll
        for (int off = 16; off; off >>= 1)
            den[r] += __shfl_xor_sync(0xffffffffu, den[r], off);
    }
#pragma unroll
    for (int r = 0; r < 4; r++) {
        float inv = 1.0f / den[r];
        float4 o;
        o.x = eluf(acc[r].x * inv);
        o.y = eluf(acc[r].y * inv);
        o.z = eluf(acc[r].z * inv);
        o.w = eluf(acc[r].w * inv);
        *(float4*)&d_gates[g][(n0 + r) * DD + lane * 4] = o;
    }
}

// ---------------- LSTM cell update ----------------
__global__ void k_cell() {
    int idx = blockIdx.x * blockDim.x + threadIdx.x;
    if (idx >= NN * DD) return;
    float g0 = d_gates[0][idx], g1 = d_gates[1][idx];
    float g2 = d_gates[2][idx], g3 = d_gates[3][idx];
    float fg = 1.f / (1.f + expf(-g0));
    float ig = 1.f / (1.f + expf(-g1));
    float cc = tanhf(g2);
    float og = 1.f / (1.f + expf(-g3));
    float c = d_cell[idx] * fg + ig * cc;
    d_cell[idx] = c;
    d_hidden[idx] = tanhf(c) * og;
}

// ---------------- outs[t] = sigmoid(hidden @ W + b) ----------------
__global__ __launch_bounds__(256) void k_out(const float* __restrict__ W,
                                             const float* __restrict__ bb, int t) {
    __shared__ __align__(16) float As[16][68];
    __shared__ __align__(16) float Bs[16][68];
    int tid = threadIdx.x;
    int n0  = blockIdx.x * 64;
    int d0  = blockIdx.y * 64;
    int tx  = tid & 15, ty = tid >> 4;
    float acc[4][4] = {};
    int la_n = tid >> 2;
    int la_k = (tid & 3) * 4;
    int lb_k = tid >> 4;
    int lb_d = (tid & 15) * 4;
    for (int k0 = 0; k0 < 128; k0 += 16) {
        __syncthreads();
        float4 av = *(const float4*)&d_hidden[(n0 + la_n) * DD + k0 + la_k];
        As[la_k + 0][la_n] = av.x; As[la_k + 1][la_n] = av.y;
        As[la_k + 2][la_n] = av.z; As[la_k + 3][la_n] = av.w;
        *(float4*)&Bs[lb_k][lb_d] = *(const float4*)&W[(k0 + lb_k) * DD + d0 + lb_d];
        __syncthreads();
#pragma unroll
        for (int kk = 0; kk < 16; kk++) {
            float4 a = *(float4*)&As[kk][ty * 4];
            float4 b = *(float4*)&Bs[kk][tx * 4];
            float ar[4] = {a.x, a.y, a.z, a.w};
            float br[4] = {b.x, b.y, b.z, b.w};
#pragma unroll
            for (int i = 0; i < 4; i++)
#pragma unroll
                for (int j = 0; j < 4; j++) acc[i][j] = fmaf(ar[i], br[j], acc[i][j]);
        }
    }
#pragma unroll
    for (int i = 0; i < 4; i++) {
        int row = n0 + ty * 4 + i;
#pragma unroll
        for (int j = 0; j < 4; j++) {
            float v = acc[i][j] + bb[d0 + tx * 4 + j];
            d_outs[t][row * DD + d0 + tx * 4 + j] = 1.f / (1.f + expf(-v));
        }
    }
}

// ---------------- conv layer: GEMM over k = s*128+c ----------------
__global__ __launch_bounds__(256) void k_conv(int l, const float* __restrict__ convb,
                                              float* __restrict__ outp) {
    __shared__ __align__(16) float As[16][68];
    __shared__ __align__(16) float Bs[16][68];
    const float* src;
    float* dst;
    if (l == 0)      { src = &d_outs[0][0]; dst = &d_y1[0][0]; }
    else if (l == 1) { src = &d_y1[0][0];   dst = &d_y2[0][0]; }
    else             { src = &d_y2[0][0];   dst = outp; }
    int tid  = threadIdx.x;
    int n0   = blockIdx.x * 64;
    int d0   = (blockIdx.y & 1) * 64;
    int tout = blockIdx.y >> 1;
    src += (size_t)tout * NN * DD;
    dst += (size_t)tout * NN * DD;
    int tx  = tid & 15, ty = tid >> 4;
    float acc[4][4] = {};
    int la_n = tid >> 2;
    int la_k = (tid & 3) * 4;
    int lb_k = tid >> 4;
    int lb_d = (tid & 15) * 4;
    for (int k0 = 0; k0 < 256; k0 += 16) {
        __syncthreads();
        int f = k0 + la_k;
        int s = f >> 7, c = f & 127;
        float4 av = *(const float4*)&src[(size_t)s * NN * DD + (n0 + la_n) * DD + c];
        As[la_k + 0][la_n] = av.x; As[la_k + 1][la_n] = av.y;
        As[la_k + 2][la_n] = av.z; As[la_k + 3][la_n] = av.w;
        *(float4*)&Bs[lb_k][lb_d] = *(const float4*)&d_convwT[l][k0 + lb_k][d0 + lb_d];
        __syncthreads();
#pragma unroll
        for (int kk = 0; kk < 16; kk++) {
            float4 a = *(float4*)&As[kk][ty * 4];
            float4 b = *(float4*)&Bs[kk][tx * 4];
            float ar[4] = {a.x, a.y, a.z, a.w};
            float br[4] = {b.x, b.y, b.z, b.w};
#pragma unroll
            for (int i = 0; i < 4; i++)
#pragma unroll
                for (int j = 0; j < 4; j++) acc[i][j] = fmaf(ar[i], br[j], acc[i][j]);
        }
    }
#pragma unroll
    for (int i = 0; i < 4; i++) {
        int row = n0 + ty * 4 + i;
#pragma unroll
        for (int j = 0; j < 4; j++) {
            int o = d0 + tx * 4 + j;
            dst[row * DD + o] = acc[i][j] + convb[l * 128 + o];
        }
    }
}

extern "C" void kernel_launch(void* const* d_in, const int* in_sizes, int n_in,
                              void* d_out, int out_size) {
    const float* actors = (const float*)d_in[0];
    const int*   G      = (const int*)d_in[1];
    const float* Wg     = (const float*)d_in[2];
    const float* ag     = (const float*)d_in[3];
    const float* W      = (const float*)d_in[4];
    const float* b      = (const float*)d_in[5];
    const float* h0     = (const float*)d_in[6];
    const float* convw  = (const float*)d_in[7];
    const float* convb  = (const float*)d_in[8];
    float* out = (float*)d_out;

    k_init<<<1024, 256>>>(actors, h0);
    k_pack<<<65536, 256>>>(G);
    k_transposeW<<<384, 256>>>(convw);

    for (int t = 0; t < 4; t++) {
        k_wh<<<dim3(32, 8), 256>>>(actors, Wg, t);
        k_prep<<<1024, 256>>>(ag);
        k_attn<<<dim3(64, 4), 256>>>(t);
        k_cell<<<1024, 256>>>();
        k_out<<<dim3(32, 2), 256>>>(W, b, t);
    }

    k_conv<<<dim3(32, 6), 256>>>(0, convb, out);
    k_conv<<<dim3(32, 4), 256>>>(1, convb, out);
    k_conv<<<dim3(32, 2), 256>>>(2, convb, out);
}